// round 15
// baseline (speedup 1.0000x reference)
#include <cuda_runtime.h>
#include <math.h>

#define TT 5
#define ZZ 32
#define YY 512
#define XX 512
#define N_RAYS 10000
#define N_STEPS 768
#define VOXEL 0.2f
#define BREAK_S 11.0f      // tail <= e^-11 * 768 * 0.2 ~ 2.6e-3 m: << budget
#define BATCH 16           // steps per ray per iteration (4 per sub-lane)
#define N_BATCH (N_STEPS / BATCH)   // 48
// Batches [0, SAFE_BATCHES) sample steps t <= 240.5 < 246 <= min distance to
// any x/y boundary (ox,oy in [246,266], |ux|,|uy| <= 1), so x/y are provably
// in-bounds and only the z-slab needs checking.
#define SAFE_BATCHES 15

// Cross-launch-safe accumulators: zero at module load; last block resets them
// at the end of every launch, so each graph replay sees zeros.
__device__ float g_acc[3] = {0.0f, 0.0f, 0.0f};
__device__ unsigned int g_count = 0u;

__global__ void __launch_bounds__(128)
ray_march_loss_kernel(const float* __restrict__ grid,
                      const float* __restrict__ origin,   // [T,3]
                      const float* __restrict__ points,   // [N_RAYS,3]
                      const int*   __restrict__ tindex,   // [N_RAYS]
                      float* __restrict__ out)            // [3]
{
    const unsigned FULL = 0xffffffffu;
    int lane = threadIdx.x & 31;
    int wid  = threadIdx.x >> 5;            // warp in block (0..3)
    int sub  = lane & 3;                    // sub-lane within quad
    int ray  = blockIdx.x * 32 + (threadIdx.x >> 2);   // 4 threads per ray
    bool have_ray = (ray < N_RAYS);

    __shared__ float s1[4], s2[4], s3[4];
    __shared__ bool  s_last;

    float gt = 0.0f, pred = 0.0f;

    float ox = 0, oy = 0, oz = 0, ux = 0, uy = 0, uz = 0;
    const float* base = grid;
    int k_exit = 0;

    if (have_ray) {
        const float offx = -51.2f, offy = -51.2f, offz = -3.2f;
        const float inv_vox = 5.0f;

        int ti = tindex[ray];

        ox = (origin[ti * 3 + 0] - offx) * inv_vox;
        oy = (origin[ti * 3 + 1] - offy) * inv_vox;
        oz = (origin[ti * 3 + 2] - offz) * inv_vox;

        float px = (points[ray * 3 + 0] - offx) * inv_vox;
        float py = (points[ray * 3 + 1] - offy) * inv_vox;
        float pz = (points[ray * 3 + 2] - offz) * inv_vox;

        float dx = px - ox, dy = py - oy, dz = pz - oz;
        float d2 = fmaxf(dx * dx + dy * dy + dz * dz, 1e-12f);
        float rinv = rsqrtf(d2);              // = 1/|dirv|
        gt = d2 * rinv;                       // = |dirv|
        ux = dx * rinv; uy = dy * rinv; uz = dz * rinv;

        base = grid + ((size_t)ti << 23);     // ti * 32*512*512

        // Exit-only clip (origin inside box; per-sample bounds guard keeps
        // exactness regardless — this is purely a work bound).
        float tex = (fabsf(ux) > 1e-8f)
                  ? __fdividef((ux > 0.0f ? (float)XX : 0.0f) - ox, ux) : 1e9f;
        float tey = (fabsf(uy) > 1e-8f)
                  ? __fdividef((uy > 0.0f ? (float)YY : 0.0f) - oy, uy) : 1e9f;
        float tez = (fabsf(uz) > 1e-8f)
                  ? __fdividef((uz > 0.0f ? (float)ZZ : 0.0f) - oz, uz) : 1e9f;
        float te = fminf(tex, fminf(tey, tez));
        if (te < 0.0f) te = (float)N_STEPS;   // degenerate: full march
        k_exit = min(N_STEPS - 1, (int)te + 1);
    }

    float S = 0.0f;                           // cumulative tau (quad-uniform)
    bool alive = have_ray;

    // ============ Phase A: batches 0..14 (steps < 240) — z-only guard =======
    #pragma unroll 1
    for (int b = 0; b < SAFE_BATCHES; ++b) {
        if (!__ballot_sync(FULL, alive)) break;

        int k0 = b * BATCH + sub * 4;
        float tf = (float)k0 + 0.5f;

        float tau[4];
        #pragma unroll
        for (int j = 0; j < 4; ++j) {
            float t = tf + (float)j;
            float fx = ox + ux * t;
            float fy = oy + uy * t;
            float fz = oz + uz * t;
            int ix = __float2int_rd(fx);
            int iy = __float2int_rd(fy);
            int iz = __float2int_rd(fz);
            // x,y provably in-bounds for t <= 240.5; z is the only live axis.
            bool inb = alive & ((unsigned)iz < ZZ);
            float v = 0.0f;
            if (inb)
                v = __ldg(base + (((iz << 9) + iy) << 9) + ix);
            tau[j] = fmaxf(v, 0.0f);
        }

        // Lane-local prefix
        float c1 = tau[0];
        float c2 = c1 + tau[1];
        float c3 = c2 + tau[2];
        float lsum = c3 + tau[3];

        // 2-level inclusive scan across the quad
        float sc = lsum;
        float v1 = __shfl_up_sync(FULL, sc, 1, 4); if (sub >= 1) sc += v1;
        float v2 = __shfl_up_sync(FULL, sc, 2, 4); if (sub >= 2) sc += v2;
        float tot  = __shfl_sync(FULL, sc, 3, 4);
        float excl = sc - lsum;

        // 5 independent exponentials
        float s0 = S + excl;
        float e0 = __expf(-s0);
        float e1 = __expf(-(s0 + c1));
        float e2 = __expf(-(s0 + c2));
        float e3 = __expf(-(s0 + c3));
        float e4 = __expf(-(s0 + lsum));

        pred += (e0 - e1) * tf
              + (e1 - e2) * (tf + 1.0f)
              + (e2 - e3) * (tf + 2.0f)
              + (e3 - e4) * (tf + 3.0f);

        S += tot;
        alive = alive && (S <= BREAK_S) && ((b + 1) * BATCH <= k_exit);
    }

    // ============ Phase B: rare batches 15..47 — full 3-axis guard ==========
    #pragma unroll 1
    for (int b = SAFE_BATCHES; b < N_BATCH; ++b) {
        if (!__ballot_sync(FULL, alive)) break;

        int k0 = b * BATCH + sub * 4;
        float tf = (float)k0 + 0.5f;

        float tau[4];
        #pragma unroll
        for (int j = 0; j < 4; ++j) {
            float t = tf + (float)j;
            float fx = ox + ux * t;
            float fy = oy + uy * t;
            float fz = oz + uz * t;
            int ix = __float2int_rd(fx);
            int iy = __float2int_rd(fy);
            int iz = __float2int_rd(fz);
            bool inb = alive &
                       ((unsigned)ix < XX) & ((unsigned)iy < YY) &
                       ((unsigned)iz < ZZ);
            float v = 0.0f;
            if (inb)
                v = __ldg(base + (((iz << 9) + iy) << 9) + ix);
            tau[j] = fmaxf(v, 0.0f);
        }

        float c1 = tau[0];
        float c2 = c1 + tau[1];
        float c3 = c2 + tau[2];
        float lsum = c3 + tau[3];

        float sc = lsum;
        float v1 = __shfl_up_sync(FULL, sc, 1, 4); if (sub >= 1) sc += v1;
        float v2 = __shfl_up_sync(FULL, sc, 2, 4); if (sub >= 2) sc += v2;
        float tot  = __shfl_sync(FULL, sc, 3, 4);
        float excl = sc - lsum;

        float s0 = S + excl;
        float e0 = __expf(-s0);
        float e1 = __expf(-(s0 + c1));
        float e2 = __expf(-(s0 + c2));
        float e3 = __expf(-(s0 + c3));
        float e4 = __expf(-(s0 + lsum));

        pred += (e0 - e1) * tf
              + (e1 - e2) * (tf + 1.0f)
              + (e2 - e3) * (tf + 2.0f)
              + (e3 - e4) * (tf + 3.0f);

        S += tot;
        alive = alive && (S <= BREAK_S) && ((b + 1) * BATCH <= k_exit);
    }

    // Combine quad partials of pred
    pred += __shfl_xor_sync(FULL, pred, 1, 4);
    pred += __shfl_xor_sync(FULL, pred, 2, 4);

    // Per-ray loss on sub-lane 0 only
    float l1 = 0.0f, l2 = 0.0f, l3 = 0.0f;
    if (have_ray && sub == 0) {
        float p = pred * VOXEL;
        float g = gt * VOXEL;
        float d = g - p;
        float ad = fabsf(d);
        l1 = ad;
        l2 = 0.5f * d * d;
        l3 = ad / fmaxf(g, 1e-6f);
    }

    // Warp reduce
    #pragma unroll
    for (int o = 16; o > 0; o >>= 1) {
        l1 += __shfl_xor_sync(FULL, l1, o);
        l2 += __shfl_xor_sync(FULL, l2, o);
        l3 += __shfl_xor_sync(FULL, l3, o);
    }

    if (lane == 0) {
        s1[wid] = l1; s2[wid] = l2; s3[wid] = l3;
    }
    __syncthreads();
    if (threadIdx.x == 0) {
        float a = 0.0f, b2 = 0.0f, c2 = 0.0f;
        #pragma unroll
        for (int i = 0; i < 4; ++i) { a += s1[i]; b2 += s2[i]; c2 += s3[i]; }
        atomicAdd(&g_acc[0], a);
        atomicAdd(&g_acc[1], b2);
        atomicAdd(&g_acc[2], c2);
        __threadfence();
        unsigned int prev = atomicAdd(&g_count, 1u);
        s_last = (prev == gridDim.x - 1);
    }
    __syncthreads();

    // Last block: publish result and reset accumulators for next replay
    if (s_last && threadIdx.x == 0) {
        const float inv_count = 1.0f / (float)N_RAYS;
        volatile float* acc = g_acc;
        float a = acc[0], b2 = acc[1], c2 = acc[2];
        out[0] = a  * inv_count;
        out[1] = b2 * inv_count;
        out[2] = c2 * inv_count;
        g_acc[0] = 0.0f; g_acc[1] = 0.0f; g_acc[2] = 0.0f;
        g_count = 0u;
        __threadfence();
    }
}

extern "C" void kernel_launch(void* const* d_in, const int* in_sizes, int n_in,
                              void* d_out, int out_size)
{
    const float* grid    = (const float*)d_in[0];  // [1,5,32,512,512]
    const float* origin  = (const float*)d_in[1];  // [1,5,3]
    const float* points  = (const float*)d_in[2];  // [1,10000,3]
    const int*   tindex  = (const int*)d_in[3];    // [1,10000]
    float* out = (float*)d_out;

    // 32 rays per 128-thread block (4 lanes per ray); 313 blocks
    int blocks = (N_RAYS + 31) / 32;   // 313
    ray_march_loss_kernel<<<blocks, 128>>>(grid, origin, points, tindex, out);
}

// round 16
// speedup vs baseline: 1.0029x; 1.0029x over previous
#include <cuda_runtime.h>
#include <math.h>

#define TT 5
#define ZZ 32
#define YY 512
#define XX 512
#define N_RAYS 10000
#define N_STEPS 768
#define VOXEL 0.2f
#define BREAK_S 11.0f      // tail <= e^-11 * 768 * 0.2 ~ 2.6e-3 m: << budget
#define BATCH 16           // steps per ray per iteration (4 per sub-lane)
#define N_BATCH (N_STEPS / BATCH)   // 48
// Batches [0, SAFE_BATCHES) sample steps t <= 240.5 < 246 <= min distance to
// any x/y boundary (ox,oy in [246,266], |ux|,|uy| <= 1), so x/y are provably
// in-bounds and only the z-slab needs checking.
#define SAFE_BATCHES 15

// Cross-launch-safe accumulators: zero at module load; last block resets them
// at the end of every launch, so each graph replay sees zeros.
__device__ float g_acc[3] = {0.0f, 0.0f, 0.0f};
__device__ unsigned int g_count = 0u;

__global__ void __launch_bounds__(128)
ray_march_loss_kernel(const float* __restrict__ grid,
                      const float* __restrict__ origin,   // [T,3]
                      const float* __restrict__ points,   // [N_RAYS,3]
                      const int*   __restrict__ tindex,   // [N_RAYS]
                      float* __restrict__ out)            // [3]
{
    const unsigned FULL = 0xffffffffu;
    int lane = threadIdx.x & 31;
    int wid  = threadIdx.x >> 5;            // warp in block (0..3)
    int sub  = lane & 3;                    // sub-lane within quad
    int ray  = blockIdx.x * 32 + (threadIdx.x >> 2);   // 4 threads per ray
    bool have_ray = (ray < N_RAYS);

    __shared__ float s1[4], s2[4], s3[4];
    __shared__ bool  s_last;

    float gt = 0.0f, pred = 0.0f;

    float ox = 0, oy = 0, oz = 0, ux = 0, uy = 0, uz = 0;
    const float* base = grid;
    int k_exit = 0;

    float tau[4];                           // current batch taus
    tau[0] = tau[1] = tau[2] = tau[3] = 0.0f;

    if (have_ray) {
        const float offx = -51.2f, offy = -51.2f, offz = -3.2f;
        const float inv_vox = 5.0f;

        int ti = tindex[ray];

        ox = (origin[ti * 3 + 0] - offx) * inv_vox;
        oy = (origin[ti * 3 + 1] - offy) * inv_vox;
        oz = (origin[ti * 3 + 2] - offz) * inv_vox;

        float px = (points[ray * 3 + 0] - offx) * inv_vox;
        float py = (points[ray * 3 + 1] - offy) * inv_vox;
        float pz = (points[ray * 3 + 2] - offz) * inv_vox;

        float dx = px - ox, dy = py - oy, dz = pz - oz;
        float d2 = fmaxf(dx * dx + dy * dy + dz * dz, 1e-12f);
        float rinv = rsqrtf(d2);              // = 1/|dirv|
        gt = d2 * rinv;                       // = |dirv|
        ux = dx * rinv; uy = dy * rinv; uz = dz * rinv;

        base = grid + ((size_t)ti << 23);     // ti * 32*512*512

        // === Issue batch-0 gathers NOW (z-only guard); clip overlaps them ===
        #pragma unroll
        for (int j = 0; j < 4; ++j) {
            float t = (float)(sub * 4 + j) + 0.5f;
            float fx = ox + ux * t;
            float fy = oy + uy * t;
            float fz = oz + uz * t;
            int ix = __float2int_rd(fx);
            int iy = __float2int_rd(fy);
            int iz = __float2int_rd(fz);
            bool inb = ((unsigned)iz < ZZ);   // x,y provably in-bounds
            float v = 0.0f;
            if (inb)
                v = __ldg(base + (((iz << 9) + iy) << 9) + ix);
            tau[j] = fmaxf(v, 0.0f);
        }

        // Exit-only clip (origin inside box; per-sample bounds guard keeps
        // exactness regardless — this is purely a work bound).
        float tex = (fabsf(ux) > 1e-8f)
                  ? __fdividef((ux > 0.0f ? (float)XX : 0.0f) - ox, ux) : 1e9f;
        float tey = (fabsf(uy) > 1e-8f)
                  ? __fdividef((uy > 0.0f ? (float)YY : 0.0f) - oy, uy) : 1e9f;
        float tez = (fabsf(uz) > 1e-8f)
                  ? __fdividef((uz > 0.0f ? (float)ZZ : 0.0f) - oz, uz) : 1e9f;
        float te = fminf(tex, fminf(tey, tez));
        if (te < 0.0f) te = (float)N_STEPS;   // degenerate: full march
        k_exit = min(N_STEPS - 1, (int)te + 1);
    }

    float S = 0.0f;                           // cumulative tau (quad-uniform)
    bool alive = have_ray;

    // ===== Phase A: batches 0..14 (steps < 240), z-only guard, prefetch =====
    #pragma unroll 1
    for (int b = 0; b < SAFE_BATCHES; ++b) {
        // --- Speculative prefetch of batch b+1 (independent of this batch's
        //     S; predicated on bounds + stale alive, both S-independent).
        float nxt[4];
        bool pf = alive && (b + 1 < SAFE_BATCHES);
        #pragma unroll
        for (int j = 0; j < 4; ++j) {
            float t = (float)((b + 1) * BATCH + sub * 4 + j) + 0.5f;
            float fz = oz + uz * t;
            int iz = __float2int_rd(fz);
            bool inb = pf & ((unsigned)iz < ZZ);
            float v = 0.0f;
            if (inb) {
                float fx = ox + ux * t;
                float fy = oy + uy * t;
                int ix = __float2int_rd(fx);
                int iy = __float2int_rd(fy);
                v = __ldg(base + (((iz << 9) + iy) << 9) + ix);
            }
            nxt[j] = fmaxf(v, 0.0f);
        }

        // --- Process current batch
        int k0 = b * BATCH + sub * 4;
        float tf = (float)k0 + 0.5f;

        float c1 = tau[0];
        float c2 = c1 + tau[1];
        float c3 = c2 + tau[2];
        float lsum = c3 + tau[3];

        float sc = lsum;
        float v1 = __shfl_up_sync(FULL, sc, 1, 4); if (sub >= 1) sc += v1;
        float v2 = __shfl_up_sync(FULL, sc, 2, 4); if (sub >= 2) sc += v2;
        float tot  = __shfl_sync(FULL, sc, 3, 4);
        float excl = sc - lsum;

        float s0 = S + excl;
        float e0 = __expf(-s0);
        float e1 = __expf(-(s0 + c1));
        float e2 = __expf(-(s0 + c2));
        float e3 = __expf(-(s0 + c3));
        float e4 = __expf(-(s0 + lsum));

        pred += (e0 - e1) * tf
              + (e1 - e2) * (tf + 1.0f)
              + (e2 - e3) * (tf + 2.0f)
              + (e3 - e4) * (tf + 3.0f);

        S += tot;
        alive = alive && (S <= BREAK_S) && ((b + 1) * BATCH <= k_exit);
        if (!__ballot_sync(FULL, alive)) { b = SAFE_BATCHES; break; }

        tau[0] = nxt[0]; tau[1] = nxt[1]; tau[2] = nxt[2]; tau[3] = nxt[3];
    }

    // ===== Phase B: rare batches 15..47, full 3-axis guard, no prefetch =====
    #pragma unroll 1
    for (int b = SAFE_BATCHES; b < N_BATCH; ++b) {
        if (!__ballot_sync(FULL, alive)) break;

        int k0 = b * BATCH + sub * 4;
        float tf = (float)k0 + 0.5f;

        float tb[4];
        #pragma unroll
        for (int j = 0; j < 4; ++j) {
            float t = tf + (float)j;
            float fx = ox + ux * t;
            float fy = oy + uy * t;
            float fz = oz + uz * t;
            int ix = __float2int_rd(fx);
            int iy = __float2int_rd(fy);
            int iz = __float2int_rd(fz);
            bool inb = alive &
                       ((unsigned)ix < XX) & ((unsigned)iy < YY) &
                       ((unsigned)iz < ZZ);
            float v = 0.0f;
            if (inb)
                v = __ldg(base + (((iz << 9) + iy) << 9) + ix);
            tb[j] = fmaxf(v, 0.0f);
        }

        float c1 = tb[0];
        float c2 = c1 + tb[1];
        float c3 = c2 + tb[2];
        float lsum = c3 + tb[3];

        float sc = lsum;
        float v1 = __shfl_up_sync(FULL, sc, 1, 4); if (sub >= 1) sc += v1;
        float v2 = __shfl_up_sync(FULL, sc, 2, 4); if (sub >= 2) sc += v2;
        float tot  = __shfl_sync(FULL, sc, 3, 4);
        float excl = sc - lsum;

        float s0 = S + excl;
        float e0 = __expf(-s0);
        float e1 = __expf(-(s0 + c1));
        float e2 = __expf(-(s0 + c2));
        float e3 = __expf(-(s0 + c3));
        float e4 = __expf(-(s0 + lsum));

        pred += (e0 - e1) * tf
              + (e1 - e2) * (tf + 1.0f)
              + (e2 - e3) * (tf + 2.0f)
              + (e3 - e4) * (tf + 3.0f);

        S += tot;
        alive = alive && (S <= BREAK_S) && ((b + 1) * BATCH <= k_exit);
    }

    // Combine quad partials of pred
    pred += __shfl_xor_sync(FULL, pred, 1, 4);
    pred += __shfl_xor_sync(FULL, pred, 2, 4);

    // Per-ray loss on sub-lane 0 only
    float l1 = 0.0f, l2 = 0.0f, l3 = 0.0f;
    if (have_ray && sub == 0) {
        float p = pred * VOXEL;
        float g = gt * VOXEL;
        float d = g - p;
        float ad = fabsf(d);
        l1 = ad;
        l2 = 0.5f * d * d;
        l3 = ad / fmaxf(g, 1e-6f);
    }

    // Warp reduce
    #pragma unroll
    for (int o = 16; o > 0; o >>= 1) {
        l1 += __shfl_xor_sync(FULL, l1, o);
        l2 += __shfl_xor_sync(FULL, l2, o);
        l3 += __shfl_xor_sync(FULL, l3, o);
    }

    if (lane == 0) {
        s1[wid] = l1; s2[wid] = l2; s3[wid] = l3;
    }
    __syncthreads();
    if (threadIdx.x == 0) {
        float a = 0.0f, b2 = 0.0f, c2 = 0.0f;
        #pragma unroll
        for (int i = 0; i < 4; ++i) { a += s1[i]; b2 += s2[i]; c2 += s3[i]; }
        atomicAdd(&g_acc[0], a);
        atomicAdd(&g_acc[1], b2);
        atomicAdd(&g_acc[2], c2);
        __threadfence();
        unsigned int prev = atomicAdd(&g_count, 1u);
        s_last = (prev == gridDim.x - 1);
    }
    __syncthreads();

    // Last block: publish result and reset accumulators for next replay
    if (s_last && threadIdx.x == 0) {
        const float inv_count = 1.0f / (float)N_RAYS;
        volatile float* acc = g_acc;
        float a = acc[0], b2 = acc[1], c2 = acc[2];
        out[0] = a  * inv_count;
        out[1] = b2 * inv_count;
        out[2] = c2 * inv_count;
        g_acc[0] = 0.0f; g_acc[1] = 0.0f; g_acc[2] = 0.0f;
        g_count = 0u;
        __threadfence();
    }
}

extern "C" void kernel_launch(void* const* d_in, const int* in_sizes, int n_in,
                              void* d_out, int out_size)
{
    const float* grid    = (const float*)d_in[0];  // [1,5,32,512,512]
    const float* origin  = (const float*)d_in[1];  // [1,5,3]
    const float* points  = (const float*)d_in[2];  // [1,10000,3]
    const int*   tindex  = (const int*)d_in[3];    // [1,10000]
    float* out = (float*)d_out;

    // 32 rays per 128-thread block (4 lanes per ray); 313 blocks
    int blocks = (N_RAYS + 31) / 32;   // 313
    ray_march_loss_kernel<<<blocks, 128>>>(grid, origin, points, tindex, out);
}

// round 17
// speedup vs baseline: 1.0238x; 1.0208x over previous
#include <cuda_runtime.h>
#include <math.h>

#define TT 5
#define ZZ 32
#define YY 512
#define XX 512
#define N_RAYS 10000
#define N_STEPS 768
#define VOXEL 0.2f
#define BREAK_S 11.0f      // tail <= e^-11 * 768 * 0.2 ~ 2.6e-3 m: << budget
#define BATCH 16           // steps per ray per iteration (4 per sub-lane)
#define N_BATCH (N_STEPS / BATCH)   // 48

// Cross-launch-safe accumulators: zero at module load; last block resets them
// at the end of every launch, so each graph replay sees zeros.
__device__ float g_acc[3] = {0.0f, 0.0f, 0.0f};
__device__ unsigned int g_count = 0u;

__global__ void __launch_bounds__(128)
ray_march_loss_kernel(const float* __restrict__ grid,
                      const float* __restrict__ origin,   // [T,3]
                      const float* __restrict__ points,   // [N_RAYS,3]
                      const int*   __restrict__ tindex,   // [N_RAYS]
                      float* __restrict__ out)            // [3]
{
    const unsigned FULL = 0xffffffffu;
    int lane = threadIdx.x & 31;
    int wid  = threadIdx.x >> 5;            // warp in block (0..3)
    int sub  = lane & 3;                    // sub-lane within quad
    int ray  = blockIdx.x * 32 + (threadIdx.x >> 2);   // 4 threads per ray
    bool have_ray = (ray < N_RAYS);

    __shared__ float s1[4], s2[4], s3[4];
    __shared__ bool  s_last;

    float gt = 0.0f, pred = 0.0f;

    float ox = 0, oy = 0, oz = 0, ux = 0, uy = 0, uz = 0;
    const float* base = grid;
    int k_exit = 0;

    if (have_ray) {
        const float offx = -51.2f, offy = -51.2f, offz = -3.2f;
        const float inv_vox = 5.0f;

        int ti = tindex[ray];

        ox = (origin[ti * 3 + 0] - offx) * inv_vox;
        oy = (origin[ti * 3 + 1] - offy) * inv_vox;
        oz = (origin[ti * 3 + 2] - offz) * inv_vox;

        float px = (points[ray * 3 + 0] - offx) * inv_vox;
        float py = (points[ray * 3 + 1] - offy) * inv_vox;
        float pz = (points[ray * 3 + 2] - offz) * inv_vox;

        float dx = px - ox, dy = py - oy, dz = pz - oz;
        float d2 = dx * dx + dy * dy + dz * dz;
        float rinv = rsqrtf(fmaxf(d2, 1e-12f));
        gt = d2 * rinv;                       // |dirv|
        float s = __fdividef(1.0f, fmaxf(gt, 1e-6f));
        ux = dx * s; uy = dy * s; uz = dz * s;

        base = grid + ((size_t)ti << 23);     // ti * 32*512*512

        // Exit-only clip (origin inside box; per-sample bounds guard keeps
        // exactness regardless — this is purely a work bound).
        float tex = (fabsf(ux) > 1e-8f)
                  ? __fdividef((ux > 0.0f ? (float)XX : 0.0f) - ox, ux) : 1e9f;
        float tey = (fabsf(uy) > 1e-8f)
                  ? __fdividef((uy > 0.0f ? (float)YY : 0.0f) - oy, uy) : 1e9f;
        float tez = (fabsf(uz) > 1e-8f)
                  ? __fdividef((uz > 0.0f ? (float)ZZ : 0.0f) - oz, uz) : 1e9f;
        float te = fminf(tex, fminf(tey, tez));
        if (te < 0.0f) te = (float)N_STEPS;   // degenerate: full march
        k_exit = min(N_STEPS - 1, (int)te + 1);
    }

    float S = 0.0f;                           // cumulative tau (quad-uniform)
    bool alive = have_ray;

    #pragma unroll 1
    for (int b = 0; b < N_BATCH; ++b) {
        if (!__ballot_sync(FULL, alive)) break;

        int k0 = b * BATCH + sub * 4;         // this sub-lane's 4 steps

        // 4 independent gathers
        float tau[4];
        #pragma unroll
        for (int j = 0; j < 4; ++j) {
            float t = (float)(k0 + j) + 0.5f;
            float fx = ox + ux * t;
            float fy = oy + uy * t;
            float fz = oz + uz * t;
            int ix = __float2int_rd(fx);
            int iy = __float2int_rd(fy);
            int iz = __float2int_rd(fz);
            bool inb = alive &
                       ((unsigned)ix < XX) & ((unsigned)iy < YY) &
                       ((unsigned)iz < ZZ);
            float v = 0.0f;
            if (inb)
                v = __ldg(base + (((iz << 9) + iy) << 9) + ix);
            tau[j] = fmaxf(v, 0.0f);
        }

        float lsum = tau[0] + tau[1] + tau[2] + tau[3];

        // 2-level inclusive scan across the quad
        float sc = lsum;
        float v1 = __shfl_up_sync(FULL, sc, 1, 4);
        if (sub >= 1) sc += v1;
        float v2 = __shfl_up_sync(FULL, sc, 2, 4);
        if (sub >= 2) sc += v2;
        float tot  = __shfl_sync(FULL, sc, 3, 4);
        float excl = sc - lsum;

        // Sequential over this lane's 4 steps (5 exps, short chain)
        float Sl = S + excl;
        float tr = __expf(-Sl);
        #pragma unroll
        for (int j = 0; j < 4; ++j) {
            Sl += tau[j];
            float tn = __expf(-Sl);
            pred += (tr - tn) * ((float)(k0 + j) + 0.5f);
            tr = tn;
        }

        S += tot;
        alive = alive && (S <= BREAK_S) && ((b + 1) * BATCH <= k_exit);
    }

    // Combine quad partials of pred (2 butterfly levels)
    pred += __shfl_xor_sync(FULL, pred, 1, 4);
    pred += __shfl_xor_sync(FULL, pred, 2, 4);

    // Per-ray loss on sub-lane 0 only
    float l1 = 0.0f, l2 = 0.0f, l3 = 0.0f;
    if (have_ray && sub == 0) {
        float p = pred * VOXEL;
        float g = gt * VOXEL;
        float d = g - p;
        float ad = fabsf(d);
        l1 = ad;
        l2 = 0.5f * d * d;
        l3 = ad / fmaxf(g, 1e-6f);
    }

    // Warp reduce
    #pragma unroll
    for (int o = 16; o > 0; o >>= 1) {
        l1 += __shfl_xor_sync(FULL, l1, o);
        l2 += __shfl_xor_sync(FULL, l2, o);
        l3 += __shfl_xor_sync(FULL, l3, o);
    }

    if (lane == 0) {
        s1[wid] = l1; s2[wid] = l2; s3[wid] = l3;
    }
    __syncthreads();
    if (threadIdx.x == 0) {
        float a = 0.0f, b2 = 0.0f, c2 = 0.0f;
        #pragma unroll
        for (int i = 0; i < 4; ++i) { a += s1[i]; b2 += s2[i]; c2 += s3[i]; }
        atomicAdd(&g_acc[0], a);
        atomicAdd(&g_acc[1], b2);
        atomicAdd(&g_acc[2], c2);
        __threadfence();
        unsigned int prev = atomicAdd(&g_count, 1u);
        s_last = (prev == gridDim.x - 1);
    }
    __syncthreads();

    // Last block: publish result and reset accumulators for next replay
    if (s_last && threadIdx.x == 0) {
        const float inv_count = 1.0f / (float)N_RAYS;
        volatile float* acc = g_acc;
        float a = acc[0], b2 = acc[1], c2 = acc[2];
        out[0] = a  * inv_count;
        out[1] = b2 * inv_count;
        out[2] = c2 * inv_count;
        g_acc[0] = 0.0f; g_acc[1] = 0.0f; g_acc[2] = 0.0f;
        g_count = 0u;
        __threadfence();
    }
}

extern "C" void kernel_launch(void* const* d_in, const int* in_sizes, int n_in,
                              void* d_out, int out_size)
{
    const float* grid    = (const float*)d_in[0];  // [1,5,32,512,512]
    const float* origin  = (const float*)d_in[1];  // [1,5,3]
    const float* points  = (const float*)d_in[2];  // [1,10000,3]
    const int*   tindex  = (const int*)d_in[3];    // [1,10000]
    float* out = (float*)d_out;

    // 32 rays per 128-thread block (4 lanes per ray); 313 blocks
    int blocks = (N_RAYS + 31) / 32;   // 313
    ray_march_loss_kernel<<<blocks, 128>>>(grid, origin, points, tindex, out);
}